// round 3
// baseline (speedup 1.0000x reference)
#include <cuda_runtime.h>
#include <math.h>
#include <stdint.h>

// B=1, DIM=3, NC=512, CT=768, NT=32, HEADS=2 (-> 4 heads), NSP=256, HID=6

// ---------------- scratch ----------------
__device__ float g_Wall[512 * 288];          // shifted w1: [u][p*96 + kx*32 + o]
__device__ float g_sb1[3 * 32];              // column sums of w1 per proj
__device__ float g_S[3 * 3 * 512 * 96];      // [p][i][h][kx*32+o]
__device__ float g_QKV[3 * 4 * 768 * 256];   // [p][H][c][nsp]
__device__ float g_scores[4 * 768 * 768];    // [H][c][d]
__device__ float g_att[4 * 768 * 256];       // linear == image (3,512,512)

// ---------------- prep shifted weights ----------------
__global__ void k_prep_wall(const float* qw1, const float* kw1, const float* vw1) {
    int idx = blockIdx.x * 256 + threadIdx.x;
    if (idx >= 512 * 288) return;
    int u = idx / 288, j = idx % 288;
    int p = j / 96, r = j % 96, kx = r / 32, o = r % 32;
    const float* w1 = (p == 0) ? qw1 : ((p == 1) ? kw1 : vw1);
    int src = u + 1 - kx;
    g_Wall[idx] = (src >= 0 && src < 512) ? w1[src * 32 + o] : 0.f;
}

__global__ void k_prep_sb1(const float* qw1, const float* kw1, const float* vw1) {
    int p = blockIdx.x;
    const float* w1 = (p == 0) ? qw1 : ((p == 1) ? kw1 : vw1);
    int t = threadIdx.x, o = t & 31, seg = t >> 5;
    float s = 0.f;
    for (int u = seg * 64; u < seg * 64 + 64; ++u) s += w1[u * 32 + o];
    __shared__ float red[8][32];
    red[seg][o] = s;
    __syncthreads();
    if (seg == 0) {
        float tot = 0.f;
        #pragma unroll
        for (int q = 0; q < 8; ++q) tot += red[q][o];
        g_sb1[p * 32 + o] = tot;
    }
}

// ---------------- S = x(1536x512) @ Wall(512x288), per-proj 96-col slab ----------------
__global__ __launch_bounds__(256) void k_gemm_S(const float* x) {
    __shared__ float As[16][36];
    __shared__ float Bs[16][96];
    int m0 = blockIdx.x * 32, p = blockIdx.y, n0 = p * 96;
    int t = threadIdx.x, tx = t & 31, ty = t >> 5;
    float acc[4][3] = {};
    for (int kt = 0; kt < 32; ++kt) {
        int k0 = kt * 16;
        {
            int row = t >> 3, c2 = t & 7;
            float2 v = *(const float2*)&x[(m0 + row) * 512 + k0 + c2 * 2];
            As[c2 * 2 + 0][row] = v.x;
            As[c2 * 2 + 1][row] = v.y;
        }
        #pragma unroll
        for (int r = 0; r < 6; ++r) {
            int idx = t + 256 * r;
            Bs[idx / 96][idx % 96] = g_Wall[(k0 + idx / 96) * 288 + n0 + idx % 96];
        }
        __syncthreads();
        #pragma unroll
        for (int kk = 0; kk < 16; ++kk) {
            float a[4], b[3];
            #pragma unroll
            for (int i = 0; i < 4; ++i) a[i] = As[kk][ty * 4 + i];
            #pragma unroll
            for (int j = 0; j < 3; ++j) b[j] = Bs[kk][tx + 32 * j];
            #pragma unroll
            for (int i = 0; i < 4; ++i)
                #pragma unroll
                for (int j = 0; j < 3; ++j) acc[i][j] += a[i] * b[j];
        }
        __syncthreads();
    }
    #pragma unroll
    for (int i = 0; i < 4; ++i) {
        int m = m0 + ty * 4 + i, ich = m >> 9, h = m & 511;
        #pragma unroll
        for (int j = 0; j < 3; ++j)
            g_S[((p * 3 + ich) * 512 + h) * 96 + tx + 32 * j] = acc[i][j];
    }
}

// ---------------- fused MLP: stage1 stencil+sigmoid, stage2 GEMM+sigmoid+split ----------------
__global__ __launch_bounds__(256, 2) void k_mlp(
    const float* cw_g, const float* cb_g,
    const float* qb1, const float* qw2, const float* qb2,
    const float* kb1, const float* kw2, const float* kb2,
    const float* vb1, const float* vw2, const float* vb2)
{
    int p = blockIdx.y, c0 = blockIdx.x * 8;
    const float* b1 = (p == 0) ? qb1 : ((p == 1) ? kb1 : vb1);
    const float* w2 = (p == 0) ? qw2 : ((p == 1) ? kw2 : vw2);
    const float* b2 = (p == 0) ? qb2 : ((p == 1) ? kb2 : vb2);

    int t = threadIdx.x, lane = t & 31, wrp = t >> 5;

    __shared__ float s_S[3 * 18 * 96];
    __shared__ float s_y1[8 * 16 * 32];
    __shared__ float s_w2[16 * 32];

    int c = c0 + wrp;
    float cw[27];
    #pragma unroll
    for (int j = 0; j < 27; ++j) cw[j] = cw_g[c * 27 + j];
    float cst = cb_g[c] * g_sb1[p * 32 + lane] + b1[lane];

    float acc[8][4] = {};

    for (int hb = 0; hb < 32; ++hb) {
        int hbase = hb * 16;
        __syncthreads();
        for (int idx = t; idx < 3 * 18 * 96; idx += 256) {
            int i = idx / (18 * 96), rem = idx % (18 * 96);
            int hr = rem / 96, q = rem % 96;
            int hp = hbase - 1 + hr;
            s_S[idx] = (hp >= 0 && hp < 512) ? g_S[((p * 3 + i) * 512 + hp) * 96 + q] : 0.f;
        }
        for (int idx = t; idx < 512; idx += 256)
            s_w2[idx] = w2[(hbase + (idx >> 5)) * 32 + (idx & 31)];
        __syncthreads();

        {   // stage 1: sliding 3-row window, one channel per warp
            float r0[9], r1[9], r2[9];
            #pragma unroll
            for (int j = 0; j < 9; ++j) {
                r0[j] = s_S[((j / 3) * 18 + 0) * 96 + (j % 3) * 32 + lane];
                r1[j] = s_S[((j / 3) * 18 + 1) * 96 + (j % 3) * 32 + lane];
            }
            #pragma unroll
            for (int hh = 0; hh < 16; ++hh) {
                #pragma unroll
                for (int j = 0; j < 9; ++j)
                    r2[j] = s_S[((j / 3) * 18 + hh + 2) * 96 + (j % 3) * 32 + lane];
                float y = cst;
                #pragma unroll
                for (int j = 0; j < 9; ++j) {
                    int i = j / 3, kx = j % 3;
                    y += cw[i * 9 + 0 + kx] * r0[j];
                    y += cw[i * 9 + 3 + kx] * r1[j];
                    y += cw[i * 9 + 6 + kx] * r2[j];
                }
                s_y1[(wrp * 16 + hh) * 32 + lane] = 1.f / (1.f + __expf(-y));
                #pragma unroll
                for (int j = 0; j < 9; ++j) { r0[j] = r1[j]; r1[j] = r2[j]; }
            }
        }
        __syncthreads();

        #pragma unroll 4
        for (int hh = 0; hh < 16; ++hh) {   // stage 2: rank-16 update
            float w2v[4];
            #pragma unroll
            for (int j = 0; j < 4; ++j) w2v[j] = s_w2[hh * 32 + wrp * 4 + j];
            #pragma unroll
            for (int cc = 0; cc < 8; ++cc) {
                float yv = s_y1[(cc * 16 + hh) * 32 + lane];
                #pragma unroll
                for (int j = 0; j < 4; ++j) acc[cc][j] += yv * w2v[j];
            }
        }
    }

    int n = lane;
    #pragma unroll
    for (int cc = 0; cc < 8; ++cc)
        #pragma unroll
        for (int j = 0; j < 4; ++j) {
            int a = wrp * 4 + j;
            float v = 1.f / (1.f + __expf(-(acc[cc][j] + b2[a])));
            int H = (a & 1) * 2 + (n & 1);
            int nsp = ((a >> 1) << 4) + (n >> 1);
            g_QKV[((p * 4 + H) * 768 + (c0 + cc)) * 256 + nsp] = v;
        }
}

// ---------------- scores = Q K^T * temperature ----------------
__global__ __launch_bounds__(256) void k_gemm_qk(const float* temp) {
    int head = blockIdx.z, m0 = blockIdx.x * 128, n0 = blockIdx.y * 128;
    const float* A = g_QKV + (size_t)(0 + head) * 768 * 256;
    const float* B = g_QKV + (size_t)(4 + head) * 768 * 256;
    __shared__ float As[16][132];
    __shared__ float Bs[16][132];
    int t = threadIdx.x, tx = t & 15, ty = t >> 4;
    float acc[8][8] = {};
    for (int kt = 0; kt < 16; ++kt) {
        int k0 = kt * 16;
        #pragma unroll
        for (int r = 0; r < 2; ++r) {
            int f4 = t + 256 * r, row = f4 >> 2, c4 = f4 & 3;
            float4 va = *(const float4*)&A[(size_t)(m0 + row) * 256 + k0 + c4 * 4];
            As[c4 * 4 + 0][row] = va.x; As[c4 * 4 + 1][row] = va.y;
            As[c4 * 4 + 2][row] = va.z; As[c4 * 4 + 3][row] = va.w;
            float4 vb = *(const float4*)&B[(size_t)(n0 + row) * 256 + k0 + c4 * 4];
            Bs[c4 * 4 + 0][row] = vb.x; Bs[c4 * 4 + 1][row] = vb.y;
            Bs[c4 * 4 + 2][row] = vb.z; Bs[c4 * 4 + 3][row] = vb.w;
        }
        __syncthreads();
        #pragma unroll
        for (int kk = 0; kk < 16; ++kk) {
            float a[8], b[8];
            #pragma unroll
            for (int i = 0; i < 8; ++i) a[i] = As[kk][ty * 8 + i];
            #pragma unroll
            for (int j = 0; j < 8; ++j) b[j] = Bs[kk][tx * 8 + j];
            #pragma unroll
            for (int i = 0; i < 8; ++i)
                #pragma unroll
                for (int j = 0; j < 8; ++j) acc[i][j] += a[i] * b[j];
        }
        __syncthreads();
    }
    float tv = temp[head];
    #pragma unroll
    for (int i = 0; i < 8; ++i) {
        float* dst = &g_scores[(size_t)head * 589824 + (size_t)(m0 + ty * 8 + i) * 768 + n0 + tx * 8];
        #pragma unroll
        for (int j = 0; j < 8; ++j) dst[j] = acc[i][j] * tv;
    }
}

// ---------------- softmax rows of 768 ----------------
__global__ __launch_bounds__(256) void k_softmax() {
    float* ptr = g_scores + (size_t)blockIdx.x * 768;
    int t = threadIdx.x;
    float v[3], mx = -1e30f;
    #pragma unroll
    for (int s = 0; s < 3; ++s) { v[s] = ptr[t + 256 * s]; mx = fmaxf(mx, v[s]); }
    __shared__ float red[256];
    red[t] = mx; __syncthreads();
    for (int st = 128; st > 0; st >>= 1) {
        if (t < st) red[t] = fmaxf(red[t], red[t + st]);
        __syncthreads();
    }
    mx = red[0]; __syncthreads();
    float sum = 0.f;
    #pragma unroll
    for (int s = 0; s < 3; ++s) { v[s] = __expf(v[s] - mx); sum += v[s]; }
    red[t] = sum; __syncthreads();
    for (int st = 128; st > 0; st >>= 1) {
        if (t < st) red[t] += red[t + st];
        __syncthreads();
    }
    float inv = 1.f / red[0];
    #pragma unroll
    for (int s = 0; s < 3; ++s) ptr[t + 256 * s] = v[s] * inv;
}

// ---------------- att = attn @ V ----------------
__global__ __launch_bounds__(256) void k_gemm_av() {
    int head = blockIdx.z, m0 = blockIdx.x * 128, n0 = blockIdx.y * 64;
    const float* A = g_scores + (size_t)head * 589824;
    const float* B = g_QKV + (size_t)(8 + head) * 768 * 256;
    __shared__ float As[16][132];
    __shared__ float Bs[16][68];
    int t = threadIdx.x, tx = t & 15, ty = t >> 4;
    float acc[8][4] = {};
    for (int kt = 0; kt < 48; ++kt) {
        int k0 = kt * 16;
        #pragma unroll
        for (int r = 0; r < 2; ++r) {
            int f4 = t + 256 * r, row = f4 >> 2, c4 = f4 & 3;
            float4 va = *(const float4*)&A[(size_t)(m0 + row) * 768 + k0 + c4 * 4];
            As[c4 * 4 + 0][row] = va.x; As[c4 * 4 + 1][row] = va.y;
            As[c4 * 4 + 2][row] = va.z; As[c4 * 4 + 3][row] = va.w;
        }
        {
            int row = t >> 4, c4 = t & 15;
            float4 vb = *(const float4*)&B[(size_t)(k0 + row) * 256 + n0 + c4 * 4];
            Bs[row][c4 * 4 + 0] = vb.x; Bs[row][c4 * 4 + 1] = vb.y;
            Bs[row][c4 * 4 + 2] = vb.z; Bs[row][c4 * 4 + 3] = vb.w;
        }
        __syncthreads();
        #pragma unroll
        for (int kk = 0; kk < 16; ++kk) {
            float a[8], b[4];
            #pragma unroll
            for (int i = 0; i < 8; ++i) a[i] = As[kk][ty * 8 + i];
            #pragma unroll
            for (int j = 0; j < 4; ++j) b[j] = Bs[kk][tx * 4 + j];
            #pragma unroll
            for (int i = 0; i < 8; ++i)
                #pragma unroll
                for (int j = 0; j < 4; ++j) acc[i][j] += a[i] * b[j];
        }
        __syncthreads();
    }
    #pragma unroll
    for (int i = 0; i < 8; ++i) {
        float* dst = &g_att[((size_t)head * 768 + m0 + ty * 8 + i) * 256 + n0 + tx * 4];
        #pragma unroll
        for (int j = 0; j < 4; ++j) dst[j] = acc[i][j];
    }
}

// ---------------- fused FeedForward + residual ----------------
__global__ __launch_bounds__(256) void k_ff(
    const float* x, const float* pi_w, const float* pi_b,
    const float* dw_w, const float* dw_b, const float* po_w, const float* po_b,
    float* out)
{
    __shared__ float att_s[3][10][34];
    __shared__ float y_s[12][10][34];
    __shared__ float wts[189];
    int t = threadIdx.x;
    int x0 = blockIdx.x * 32, y0 = blockIdx.y * 8;
    if (t < 36) wts[t] = pi_w[t];
    else if (t < 48) wts[t] = pi_b[t - 36];
    else if (t < 156) wts[t] = dw_w[t - 48];
    else if (t < 168) wts[t] = dw_b[t - 156];
    else if (t < 186) wts[t] = po_w[t - 168];
    else if (t < 189) wts[t] = po_b[t - 186];
    for (int idx = t; idx < 1020; idx += 256) {
        int i = idx / 340, rem = idx % 340, ly = rem / 34, lx = rem % 34;
        int gy = y0 + ly - 1, gx = x0 + lx - 1;
        att_s[i][ly][lx] = (gy >= 0 && gy < 512 && gx >= 0 && gx < 512)
                           ? g_att[(i * 512 + gy) * 512 + gx] : 0.f;
    }
    __syncthreads();
    for (int idx = t; idx < 12 * 340; idx += 256) {
        int ch = idx / 340, rem = idx % 340, ly = rem / 34, lx = rem % 34;
        int gy = y0 + ly - 1, gx = x0 + lx - 1;
        float v = 0.f;
        if (gy >= 0 && gy < 512 && gx >= 0 && gx < 512) {
            v = wts[36 + ch];
            #pragma unroll
            for (int i = 0; i < 3; ++i) v += wts[ch * 3 + i] * att_s[i][ly][lx];
        }
        y_s[ch][ly][lx] = v;
    }
    __syncthreads();
    int lx = t & 31, ly = t >> 5;
    int gx = x0 + lx, gy = y0 + ly;
    float d[12];
    #pragma unroll
    for (int ch = 0; ch < 12; ++ch) {
        float v = wts[156 + ch];
        #pragma unroll
        for (int ky = 0; ky < 3; ++ky)
            #pragma unroll
            for (int kx = 0; kx < 3; ++kx)
                v += wts[48 + ch * 9 + ky * 3 + kx] * y_s[ch][ly + ky][lx + kx];
        d[ch] = v;
    }
    float g[6];
    #pragma unroll
    for (int c6 = 0; c6 < 6; ++c6) {
        float a = d[c6];
        g[c6] = 0.5f * a * (1.f + erff(a * 0.70710678f)) * d[6 + c6];
    }
    #pragma unroll
    for (int i = 0; i < 3; ++i) {
        float v = wts[186 + i];
        #pragma unroll
        for (int c6 = 0; c6 < 6; ++c6) v += wts[168 + i * 6 + c6] * g[c6];
        out[(i * 512 + gy) * 512 + gx] = x[(i * 512 + gy) * 512 + gx] + v;
    }
}

extern "C" void kernel_launch(void* const* d_in, const int* in_sizes, int n_in,
                              void* d_out, int out_size) {
    const float* x    = (const float*)d_in[0];
    const float* c_w  = (const float*)d_in[1];
    const float* c_b  = (const float*)d_in[2];
    const float* q_w1 = (const float*)d_in[3];
    const float* q_b1 = (const float*)d_in[4];
    const float* q_w2 = (const float*)d_in[5];
    const float* q_b2 = (const float*)d_in[6];
    const float* k_w1 = (const float*)d_in[7];
    const float* k_b1 = (const float*)d_in[8];
    const float* k_w2 = (const float*)d_in[9];
    const float* k_b2 = (const float*)d_in[10];
    const float* v_w1 = (const float*)d_in[11];
    const float* v_b1 = (const float*)d_in[12];
    const float* v_w2 = (const float*)d_in[13];
    const float* v_b2 = (const float*)d_in[14];
    const float* temp = (const float*)d_in[15];
    const float* pi_w = (const float*)d_in[16];
    const float* pi_b = (const float*)d_in[17];
    const float* dw_w = (const float*)d_in[18];
    const float* dw_b = (const float*)d_in[19];
    const float* po_w = (const float*)d_in[20];
    const float* po_b = (const float*)d_in[21];
    float* out = (float*)d_out;

    k_prep_wall<<<576, 256>>>(q_w1, k_w1, v_w1);
    k_prep_sb1<<<3, 256>>>(q_w1, k_w1, v_w1);
    k_gemm_S<<<dim3(48, 3), 256>>>(x);
    k_mlp<<<dim3(96, 3), 256>>>(c_w, c_b, q_b1, q_w2, q_b2,
                                k_b1, k_w2, k_b2, v_b1, v_w2, v_b2);
    k_gemm_qk<<<dim3(6, 6, 4), 256>>>(temp);
    k_softmax<<<3072, 256>>>();
    k_gemm_av<<<dim3(6, 4, 4), 256>>>();
    k_ff<<<dim3(16, 64), 256>>>(x, pi_w, pi_b, dw_w, dw_b, po_w, po_b, out);
}

// round 5
// speedup vs baseline: 1.3101x; 1.3101x over previous
#include <cuda_runtime.h>
#include <math.h>
#include <stdint.h>

// B=1, DIM=3, NC=512, CT=768, NT=32, HEADS=2 (-> 4 heads), NSP=256

typedef unsigned long long ull;

__device__ __forceinline__ ull pk2(float lo, float hi) {
    ull r; asm("mov.b64 %0,{%1,%2};" : "=l"(r) : "f"(lo), "f"(hi)); return r;
}
__device__ __forceinline__ ull bro(float v) { return pk2(v, v); }
__device__ __forceinline__ void fma2(ull& d, ull a, ull b) {
    asm("fma.rn.f32x2 %0,%1,%2,%0;" : "+l"(d) : "l"(a), "l"(b));
}
__device__ __forceinline__ float2 up2(ull v) {
    float2 f; asm("mov.b64 {%0,%1},%2;" : "=f"(f.x), "=f"(f.y) : "l"(v)); return f;
}

// ---------------- scratch ----------------
__device__ float g_Wall[512 * 288];          // shifted w1: [u][p*96 + kx*32 + o]
__device__ float g_sb1[3 * 32];              // column sums of w1 per proj
__device__ float g_S[3 * 3 * 512 * 96];      // [p][i][h][kx*32+o]
__device__ float g_QKV[3 * 4 * 768 * 256];   // [p][H][c][nsp]
__device__ float g_scores[4 * 768 * 768];    // [H][c][d]
__device__ float g_att[4 * 768 * 256];       // linear == image (3,512,512)

// ---------------- prep shifted weights ----------------
__global__ void k_prep_wall(const float* qw1, const float* kw1, const float* vw1) {
    int idx = blockIdx.x * 256 + threadIdx.x;
    if (idx >= 512 * 288) return;
    int u = idx / 288, j = idx % 288;
    int p = j / 96, r = j % 96, kx = r / 32, o = r % 32;
    const float* w1 = (p == 0) ? qw1 : ((p == 1) ? kw1 : vw1);
    int src = u + 1 - kx;
    g_Wall[idx] = (src >= 0 && src < 512) ? w1[src * 32 + o] : 0.f;
}

__global__ void k_prep_sb1(const float* qw1, const float* kw1, const float* vw1) {
    int p = blockIdx.x;
    const float* w1 = (p == 0) ? qw1 : ((p == 1) ? kw1 : vw1);
    int t = threadIdx.x, o = t & 31, seg = t >> 5;
    float s = 0.f;
    for (int u = seg * 64; u < seg * 64 + 64; ++u) s += w1[u * 32 + o];
    __shared__ float red[8][32];
    red[seg][o] = s;
    __syncthreads();
    if (seg == 0) {
        float tot = 0.f;
        #pragma unroll
        for (int q = 0; q < 8; ++q) tot += red[q][o];
        g_sb1[p * 32 + o] = tot;
    }
}

// ---------------- S = x(1536x512) @ Wall(512x288), per-proj 96-col slab ----------------
__global__ __launch_bounds__(256) void k_gemm_S(const float* x) {
    __shared__ float As[16][36];
    __shared__ float Bs[16][96];
    int m0 = blockIdx.x * 32, p = blockIdx.y, n0 = p * 96;
    int t = threadIdx.x, tx = t & 31, ty = t >> 5;
    float acc[4][3] = {};
    for (int kt = 0; kt < 32; ++kt) {
        int k0 = kt * 16;
        {
            int row = t >> 3, c2 = t & 7;
            float2 v = *(const float2*)&x[(m0 + row) * 512 + k0 + c2 * 2];
            As[c2 * 2 + 0][row] = v.x;
            As[c2 * 2 + 1][row] = v.y;
        }
        #pragma unroll
        for (int r = 0; r < 6; ++r) {
            int idx = t + 256 * r;
            Bs[idx / 96][idx % 96] = g_Wall[(k0 + idx / 96) * 288 + n0 + idx % 96];
        }
        __syncthreads();
        #pragma unroll
        for (int kk = 0; kk < 16; ++kk) {
            float a[4], b[3];
            #pragma unroll
            for (int i = 0; i < 4; ++i) a[i] = As[kk][ty * 4 + i];
            #pragma unroll
            for (int j = 0; j < 3; ++j) b[j] = Bs[kk][tx + 32 * j];
            #pragma unroll
            for (int i = 0; i < 4; ++i)
                #pragma unroll
                for (int j = 0; j < 3; ++j) acc[i][j] += a[i] * b[j];
        }
        __syncthreads();
    }
    #pragma unroll
    for (int i = 0; i < 4; ++i) {
        int m = m0 + ty * 4 + i, ich = m >> 9, h = m & 511;
        #pragma unroll
        for (int j = 0; j < 3; ++j)
            g_S[((p * 3 + ich) * 512 + h) * 96 + tx + 32 * j] = acc[i][j];
    }
}

// ---------------- fused MLP with f32x2 packing ----------------
__global__ __launch_bounds__(256, 2) void k_mlp(
    const float* cw_g, const float* cb_g,
    const float* qb1, const float* qw2, const float* qb2,
    const float* kb1, const float* kw2, const float* kb2,
    const float* vb1, const float* vw2, const float* vb2)
{
    int p = blockIdx.y, c0 = blockIdx.x * 8;
    const float* b1 = (p == 0) ? qb1 : ((p == 1) ? kb1 : vb1);
    const float* w2 = (p == 0) ? qw2 : ((p == 1) ? kw2 : vw2);
    const float* b2 = (p == 0) ? qb2 : ((p == 1) ? kb2 : vb2);

    int t = threadIdx.x, lane = t & 31, wrp = t >> 5;

    __shared__ float s_S[3 * 18 * 96];     // stencil input tile
    __shared__ float s_y1[8 * 16 * 32];    // [c][hh][o]
    __shared__ float s_w2[16 * 32];        // [hh][o2]
    __shared__ float s_cw[27 * 8];         // [j][c] (c contiguous for LDS.64)
    __shared__ float s_cst[32 * 8];        // [o][c] : cb*sb1 + b1

    // weight prep
    if (t < 216) { int j = t >> 3, c = t & 7; s_cw[t] = cw_g[(c0 + c) * 27 + j]; }
    { int o = t >> 3, c = t & 7; s_cst[t] = cb_g[c0 + c] * g_sb1[p * 32 + o] + b1[o]; }

    ull acc2[8][2];  // stage2: [cc][o2-pair]
    #pragma unroll
    for (int cc = 0; cc < 8; ++cc) { acc2[cc][0] = 0ull; acc2[cc][1] = 0ull; }

    // stage1 thread coords: 2 adjacent o per thread
    int n0 = t * 2;
    int s1_hh = n0 >> 5, s1_o = n0 & 31;  // s1_o even
    const float* bptr = &s_S[s1_hh * 96 + s1_o];

    for (int hb = 0; hb < 32; ++hb) {
        int hbase = hb * 16;
        __syncthreads();
        // load s_S tile: 54 rows x 96 floats = 1296 float4
        {
            const float4* g4 = (const float4*)g_S;
            #pragma unroll
            for (int pass = 0; pass < 6; ++pass) {
                int idx = t + 256 * pass;
                if (idx < 1296) {
                    int r = idx / 24, cq = idx - r * 24;
                    int i = r / 18, hr = r - i * 18;
                    int hp = hbase - 1 + hr;
                    float4 v = make_float4(0.f, 0.f, 0.f, 0.f);
                    if (hp >= 0 && hp < 512) v = g4[((p * 3 + i) * 512 + hp) * 24 + cq];
                    *(float4*)&s_S[r * 96 + cq * 4] = v;
                }
            }
            for (int idx = t; idx < 512; idx += 256)
                s_w2[idx] = w2[(hbase + (idx >> 5)) * 32 + (idx & 31)];
        }
        __syncthreads();

        // ---- stage 1: K=27 rank update, 8c(4 pairs) x 2n per thread ----
        {
            ull a1[4][2];
            #pragma unroll
            for (int cp = 0; cp < 4; ++cp) {
                a1[cp][0] = *(const ull*)&s_cst[s1_o * 8 + 2 * cp];
                a1[cp][1] = *(const ull*)&s_cst[(s1_o + 1) * 8 + 2 * cp];
            }
            #pragma unroll
            for (int i = 0; i < 3; ++i)
                #pragma unroll
                for (int ky = 0; ky < 3; ++ky)
                    #pragma unroll
                    for (int kx = 0; kx < 3; ++kx) {
                        const int off = (i * 18 + ky) * 96 + kx * 32;
                        const int j = (i * 3 + ky) * 3 + kx;
                        ull bb0 = bro(bptr[off]);
                        ull bb1 = bro(bptr[off + 1]);
                        #pragma unroll
                        for (int cp = 0; cp < 4; ++cp) {
                            ull a = *(const ull*)&s_cw[j * 8 + 2 * cp];
                            fma2(a1[cp][0], a, bb0);
                            fma2(a1[cp][1], a, bb1);
                        }
                    }
            #pragma unroll
            for (int cp = 0; cp < 4; ++cp)
                #pragma unroll
                for (int nn = 0; nn < 2; ++nn) {
                    float2 y = up2(a1[cp][nn]);
                    y.x = 1.f / (1.f + __expf(-y.x));
                    y.y = 1.f / (1.f + __expf(-y.y));
                    s_y1[((2 * cp) * 16 + s1_hh) * 32 + s1_o + nn] = y.x;
                    s_y1[((2 * cp + 1) * 16 + s1_hh) * 32 + s1_o + nn] = y.y;
                }
        }
        __syncthreads();

        // ---- stage 2: rank-16 update, packed over o2 pairs ----
        #pragma unroll 4
        for (int hh = 0; hh < 16; ++hh) {
            ull w2a = *(const ull*)&s_w2[hh * 32 + wrp * 4];
            ull w2b = *(const ull*)&s_w2[hh * 32 + wrp * 4 + 2];
            #pragma unroll
            for (int cc = 0; cc < 8; ++cc) {
                ull yv = bro(s_y1[(cc * 16 + hh) * 32 + lane]);
                fma2(acc2[cc][0], yv, w2a);
                fma2(acc2[cc][1], yv, w2b);
            }
        }
    }

    // final epilogue: sigmoid + head split
    int n = lane;
    #pragma unroll
    for (int cc = 0; cc < 8; ++cc)
        #pragma unroll
        for (int jp = 0; jp < 2; ++jp) {
            float2 v = up2(acc2[cc][jp]);
            #pragma unroll
            for (int half = 0; half < 2; ++half) {
                int a = wrp * 4 + jp * 2 + half;
                float vv = (half == 0) ? v.x : v.y;
                float val = 1.f / (1.f + __expf(-(vv + b2[a])));
                int H = (a & 1) * 2 + (n & 1);
                int nsp = ((a >> 1) << 4) + (n >> 1);
                g_QKV[((p * 4 + H) * 768 + (c0 + cc)) * 256 + nsp] = val;
            }
        }
}

// ---------------- scores = Q K^T * temperature (f32x2) ----------------
__global__ __launch_bounds__(256) void k_gemm_qk(const float* temp) {
    int head = blockIdx.z, m0 = blockIdx.x * 128, n0 = blockIdx.y * 128;
    const float* A = g_QKV + (size_t)(0 + head) * 768 * 256;
    const float* B = g_QKV + (size_t)(4 + head) * 768 * 256;
    __shared__ float As[16][132];
    __shared__ float Bs[16][132];
    int t = threadIdx.x, tx = t & 15, ty = t >> 4;
    ull acc2[8][4];
    #pragma unroll
    for (int i = 0; i < 8; ++i)
        #pragma unroll
        for (int j = 0; j < 4; ++j) acc2[i][j] = 0ull;
    for (int kt = 0; kt < 16; ++kt) {
        int k0 = kt * 16;
        #pragma unroll
        for (int r = 0; r < 2; ++r) {
            int f4 = t + 256 * r, row = f4 >> 2, c4 = f4 & 3;
            float4 va = *(const float4*)&A[(size_t)(m0 + row) * 256 + k0 + c4 * 4];
            As[c4 * 4 + 0][row] = va.x; As[c4 * 4 + 1][row] = va.y;
            As[c4 * 4 + 2][row] = va.z; As[c4 * 4 + 3][row] = va.w;
            float4 vb = *(const float4*)&B[(size_t)(n0 + row) * 256 + k0 + c4 * 4];
            Bs[c4 * 4 + 0][row] = vb.x; Bs[c4 * 4 + 1][row] = vb.y;
            Bs[c4 * 4 + 2][row] = vb.z; Bs[c4 * 4 + 3][row] = vb.w;
        }
        __syncthreads();
        #pragma unroll
        for (int kk = 0; kk < 16; ++kk) {
            ull bp[4];
            #pragma unroll
            for (int jp = 0; jp < 4; ++jp) bp[jp] = *(const ull*)&Bs[kk][tx * 8 + 2 * jp];
            #pragma unroll
            for (int i = 0; i < 8; ++i) {
                ull ab = bro(As[kk][ty * 8 + i]);
                #pragma unroll
                for (int jp = 0; jp < 4; ++jp) fma2(acc2[i][jp], ab, bp[jp]);
            }
        }
        __syncthreads();
    }
    float tv = temp[head];
    #pragma unroll
    for (int i = 0; i < 8; ++i) {
        float* dst = &g_scores[(size_t)head * 589824 + (size_t)(m0 + ty * 8 + i) * 768 + n0 + tx * 8];
        #pragma unroll
        for (int jp = 0; jp < 4; ++jp) {
            float2 v = up2(acc2[i][jp]);
            dst[2 * jp] = v.x * tv;
            dst[2 * jp + 1] = v.y * tv;
        }
    }
}

// ---------------- softmax rows of 768 ----------------
__global__ __launch_bounds__(256) void k_softmax() {
    float* ptr = g_scores + (size_t)blockIdx.x * 768;
    int t = threadIdx.x;
    float v[3], mx = -1e30f;
    #pragma unroll
    for (int s = 0; s < 3; ++s) { v[s] = ptr[t + 256 * s]; mx = fmaxf(mx, v[s]); }
    __shared__ float red[256];
    red[t] = mx; __syncthreads();
    for (int st = 128; st > 0; st >>= 1) {
        if (t < st) red[t] = fmaxf(red[t], red[t + st]);
        __syncthreads();
    }
    mx = red[0]; __syncthreads();
    float sum = 0.f;
    #pragma unroll
    for (int s = 0; s < 3; ++s) { v[s] = __expf(v[s] - mx); sum += v[s]; }
    red[t] = sum; __syncthreads();
    for (int st = 128; st > 0; st >>= 1) {
        if (t < st) red[t] += red[t + st];
        __syncthreads();
    }
    float inv = 1.f / red[0];
    #pragma unroll
    for (int s = 0; s < 3; ++s) ptr[t + 256 * s] = v[s] * inv;
}

// ---------------- att = attn @ V (f32x2) ----------------
__global__ __launch_bounds__(256) void k_gemm_av() {
    int head = blockIdx.z, m0 = blockIdx.x * 128, n0 = blockIdx.y * 64;
    const float* A = g_scores + (size_t)head * 589824;
    const float* B = g_QKV + (size_t)(8 + head) * 768 * 256;
    __shared__ float As[16][132];
    __shared__ float Bs[16][68];
    int t = threadIdx.x, tx = t & 15, ty = t >> 4;
    ull acc2[8][2];
    #pragma unroll
    for (int i = 0; i < 8; ++i) { acc2[i][0] = 0ull; acc2[i][1] = 0ull; }
    for (int kt = 0; kt < 48; ++kt) {
        int k0 = kt * 16;
        #pragma unroll
        for (int r = 0; r < 2; ++r) {
            int f4 = t + 256 * r, row = f4 >> 2, c4 = f4 & 3;
            float4 va = *(const float4*)&A[(size_t)(m0 + row) * 768 + k0 + c4 * 4];
            As[c4 * 4 + 0][row] = va.x; As[c4 * 4 + 1][row] = va.y;
            As[c4 * 4 + 2][row] = va.z; As[c4 * 4 + 3][row] = va.w;
        }
        {
            int row = t >> 4, c4 = t & 15;
            float4 vb = *(const float4*)&B[(size_t)(k0 + row) * 256 + n0 + c4 * 4];
            Bs[row][c4 * 4 + 0] = vb.x; Bs[row][c4 * 4 + 1] = vb.y;
            Bs[row][c4 * 4 + 2] = vb.z; Bs[row][c4 * 4 + 3] = vb.w;
        }
        __syncthreads();
        #pragma unroll
        for (int kk = 0; kk < 16; ++kk) {
            ull bp0 = *(const ull*)&Bs[kk][tx * 4];
            ull bp1 = *(const ull*)&Bs[kk][tx * 4 + 2];
            #pragma unroll
            for (int i = 0; i < 8; ++i) {
                ull ab = bro(As[kk][ty * 8 + i]);
                fma2(acc2[i][0], ab, bp0);
                fma2(acc2[i][1], ab, bp1);
            }
        }
        __syncthreads();
    }
    #pragma unroll
    for (int i = 0; i < 8; ++i) {
        float* dst = &g_att[((size_t)head * 768 + m0 + ty * 8 + i) * 256 + n0 + tx * 4];
        float2 v0 = up2(acc2[i][0]);
        float2 v1 = up2(acc2[i][1]);
        dst[0] = v0.x; dst[1] = v0.y; dst[2] = v1.x; dst[3] = v1.y;
    }
}

// ---------------- fused FeedForward + residual ----------------
__global__ __launch_bounds__(256) void k_ff(
    const float* x, const float* pi_w, const float* pi_b,
    const float* dw_w, const float* dw_b, const float* po_w, const float* po_b,
    float* out)
{
    __shared__ float att_s[3][10][34];
    __shared__ float y_s[12][10][34];
    __shared__ float wts[189];
    int t = threadIdx.x;
    int x0 = blockIdx.x * 32, y0 = blockIdx.y * 8;
    if (t < 36) wts[t] = pi_w[t];
    else if (t < 48) wts[t] = pi_b[t - 36];
    else if (t < 156) wts[t] = dw_w[t - 48];
    else if (t < 168) wts[t] = dw_b[t - 156];
    else if (t < 186) wts[t] = po_w[t - 168];
    else if (t < 189) wts[t] = po_b[t - 186];
    for (int idx = t; idx < 1020; idx += 256) {
        int i = idx / 340, rem = idx % 340, ly = rem / 34, lx = rem % 34;
        int gy = y0 + ly - 1, gx = x0 + lx - 1;
        att_s[i][ly][lx] = (gy >= 0 && gy < 512 && gx >= 0 && gx < 512)
                           ? g_att[(i * 512 + gy) * 512 + gx] : 0.f;
    }
    __syncthreads();
    for (int idx = t; idx < 12 * 340; idx += 256) {
        int ch = idx / 340, rem = idx % 340, ly = rem / 34, lx = rem % 34;
        int gy = y0 + ly - 1, gx = x0 + lx - 1;
        float v = 0.f;
        if (gy >= 0 && gy < 512 && gx >= 0 && gx < 512) {
            v = wts[36 + ch];
            #pragma unroll
            for (int i = 0; i < 3; ++i) v += wts[ch * 3 + i] * att_s[i][ly][lx];
        }
        y_s[ch][ly][lx] = v;
    }
    __syncthreads();
    int lx = t & 31, ly = t >> 5;
    int gx = x0 + lx, gy = y0 + ly;
    float d[12];
    #pragma unroll
    for (int ch = 0; ch < 12; ++ch) {
        float v = wts[156 + ch];
        #pragma unroll
        for (int ky = 0; ky < 3; ++ky)
            #pragma unroll
            for (int kx = 0; kx < 3; ++kx)
                v += wts[48 + ch * 9 + ky * 3 + kx] * y_s[ch][ly + ky][lx + kx];
        d[ch] = v;
    }
    float g[6];
    #pragma unroll
    for (int c6 = 0; c6 < 6; ++c6) {
        float a = d[c6];
        g[c6] = 0.5f * a * (1.f + erff(a * 0.70710678f)) * d[6 + c6];
    }
    #pragma unroll
    for (int i = 0; i < 3; ++i) {
        float v = wts[186 + i];
        #pragma unroll
        for (int c6 = 0; c6 < 6; ++c6) v += wts[168 + i * 6 + c6] * g[c6];
        out[(i * 512 + gy) * 512 + gx] = x[(i * 512 + gy) * 512 + gx] + v;
    }
}

extern "C" void kernel_launch(void* const* d_in, const int* in_sizes, int n_in,
                              void* d_out, int out_size) {
    const float* x    = (const float*)d_in[0];
    const float* c_w  = (const float*)d_in[1];
    const float* c_b  = (const float*)d_in[2];
    const float* q_w1 = (const float*)d_in[3];
    const float* q_b1 = (const float*)d_in[4];
    const float* q_w2 = (const float*)d_in[5];
    const float* q_b2 = (const float*)d_in[6];
    const float* k_w1 = (const float*)d_in[7];
    const float* k_b1 = (const float*)d_in[8];
    const float* k_w2 = (const float*)d_in[9];
    const float* k_b2 = (const float*)d_in[10];
    const float* v_w1 = (const float*)d_in[11];
    const float* v_b1 = (const float*)d_in[12];
    const float* v_w2 = (const float*)d_in[13];
    const float* v_b2 = (const float*)d_in[14];
    const float* temp = (const float*)d_in[15];
    const float* pi_w = (const float*)d_in[16];
    const float* pi_b = (const float*)d_in[17];
    const float* dw_w = (const float*)d_in[18];
    const float* dw_b = (const float*)d_in[19];
    const float* po_w = (const float*)d_in[20];
    const float* po_b = (const float*)d_in[21];
    float* out = (float*)d_out;

    k_prep_wall<<<576, 256>>>(q_w1, k_w1, v_w1);
    k_prep_sb1<<<3, 256>>>(q_w1, k_w1, v_w1);
    k_gemm_S<<<dim3(48, 3), 256>>>(x);
    k_mlp<<<dim3(96, 3), 256>>>(c_w, c_b, q_b1, q_w2, q_b2,
                                k_b1, k_w2, k_b2, v_b1, v_w2, v_b2);
    k_gemm_qk<<<dim3(6, 6, 4), 256>>>(temp);
    k_softmax<<<3072, 256>>>();
    k_gemm_av<<<dim3(6, 4, 4), 256>>>();
    k_ff<<<dim3(16, 64), 256>>>(x, pi_w, pi_b, dw_w, dw_b, po_w, po_b, out);
}

// round 6
// speedup vs baseline: 1.3581x; 1.0366x over previous
#include <cuda_runtime.h>
#include <math.h>
#include <stdint.h>

// B=1, DIM=3, NC=512, CT=768, NT=32, HEADS=2 (-> 4 heads), NSP=256

typedef unsigned long long ull;

__device__ __forceinline__ ull pk2(float lo, float hi) {
    ull r; asm("mov.b64 %0,{%1,%2};" : "=l"(r) : "f"(lo), "f"(hi)); return r;
}
__device__ __forceinline__ ull bro(float v) { return pk2(v, v); }
__device__ __forceinline__ void fma2(ull& d, ull a, ull b) {
    asm("fma.rn.f32x2 %0,%1,%2,%0;" : "+l"(d) : "l"(a), "l"(b));
}
__device__ __forceinline__ float2 up2(ull v) {
    float2 f; asm("mov.b64 {%0,%1},%2;" : "=f"(f.x), "=f"(f.y) : "l"(v)); return f;
}

// ---------------- scratch ----------------
__device__ float g_Wall[512 * 288];          // shifted w1: [u][p*96 + kx*32 + o]
__device__ float g_sb1[3 * 32];              // column sums of w1 per proj
__device__ float g_S[3 * 3 * 512 * 96];      // [p][i][h][kx*32+o]
__device__ float g_QKV[3 * 4 * 768 * 256];   // [p][H][c][nsp]
__device__ float g_scores[4 * 768 * 768];    // [H][c][d]
__device__ float g_att[4 * 768 * 256];       // linear == image (3,512,512)

// ---------------- prep shifted weights ----------------
__global__ void k_prep_wall(const float* qw1, const float* kw1, const float* vw1) {
    int idx = blockIdx.x * 256 + threadIdx.x;
    if (idx >= 512 * 288) return;
    int u = idx / 288, j = idx % 288;
    int p = j / 96, r = j % 96, kx = r / 32, o = r % 32;
    const float* w1 = (p == 0) ? qw1 : ((p == 1) ? kw1 : vw1);
    int src = u + 1 - kx;
    g_Wall[idx] = (src >= 0 && src < 512) ? w1[src * 32 + o] : 0.f;
}

__global__ void k_prep_sb1(const float* qw1, const float* kw1, const float* vw1) {
    int p = blockIdx.x;
    const float* w1 = (p == 0) ? qw1 : ((p == 1) ? kw1 : vw1);
    int t = threadIdx.x, o = t & 31, seg = t >> 5;
    float s = 0.f;
    for (int u = seg * 64; u < seg * 64 + 64; ++u) s += w1[u * 32 + o];
    __shared__ float red[8][32];
    red[seg][o] = s;
    __syncthreads();
    if (seg == 0) {
        float tot = 0.f;
        #pragma unroll
        for (int q = 0; q < 8; ++q) tot += red[q][o];
        g_sb1[p * 32 + o] = tot;
    }
}

// ---------------- S = x(1536x512) @ Wall(512x288), per-proj 96-col slab ----------------
__global__ __launch_bounds__(256) void k_gemm_S(const float* x) {
    __shared__ float As[16][36];
    __shared__ float Bs[16][96];
    int m0 = blockIdx.x * 32, p = blockIdx.y, n0 = p * 96;
    int t = threadIdx.x, tx = t & 31, ty = t >> 5;
    float acc[4][3] = {};
    for (int kt = 0; kt < 32; ++kt) {
        int k0 = kt * 16;
        {
            int row = t >> 3, c2 = t & 7;
            float2 v = *(const float2*)&x[(m0 + row) * 512 + k0 + c2 * 2];
            As[c2 * 2 + 0][row] = v.x;
            As[c2 * 2 + 1][row] = v.y;
        }
        #pragma unroll
        for (int r = 0; r < 6; ++r) {
            int idx = t + 256 * r;
            Bs[idx / 96][idx % 96] = g_Wall[(k0 + idx / 96) * 288 + n0 + idx % 96];
        }
        __syncthreads();
        #pragma unroll
        for (int kk = 0; kk < 16; ++kk) {
            float a[4], b[3];
            #pragma unroll
            for (int i = 0; i < 4; ++i) a[i] = As[kk][ty * 4 + i];
            #pragma unroll
            for (int j = 0; j < 3; ++j) b[j] = Bs[kk][tx + 32 * j];
            #pragma unroll
            for (int i = 0; i < 4; ++i)
                #pragma unroll
                for (int j = 0; j < 3; ++j) acc[i][j] += a[i] * b[j];
        }
        __syncthreads();
    }
    #pragma unroll
    for (int i = 0; i < 4; ++i) {
        int m = m0 + ty * 4 + i, ich = m >> 9, h = m & 511;
        #pragma unroll
        for (int j = 0; j < 3; ++j)
            g_S[((p * 3 + ich) * 512 + h) * 96 + tx + 32 * j] = acc[i][j];
    }
}

// ---------------- fused MLP: f32x2 + double buffering ----------------
__global__ __launch_bounds__(256, 2) void k_mlp(
    const float* cw_g, const float* cb_g,
    const float* qb1, const float* qw2, const float* qb2,
    const float* kb1, const float* kw2, const float* kb2,
    const float* vb1, const float* vw2, const float* vb2)
{
    int p = blockIdx.y, c0 = blockIdx.x * 8;
    const float* b1 = (p == 0) ? qb1 : ((p == 1) ? kb1 : vb1);
    const float* w2 = (p == 0) ? qw2 : ((p == 1) ? kw2 : vw2);
    const float* b2 = (p == 0) ? qb2 : ((p == 1) ? kb2 : vb2);

    int t = threadIdx.x, lane = t & 31, wrp = t >> 5;

    __shared__ float s_S[2][54 * 96];      // double-buffered stencil input
    __shared__ float s_w2[2][16 * 32];     // double-buffered [hh][o2]
    __shared__ float s_y1[8 * 16 * 32];    // [c][hh][o]
    __shared__ float s_cw[27 * 8];         // [j][c]
    __shared__ float s_cst[32 * 8];        // [o][c] : cb*sb1 + b1

    // weight prep
    if (t < 216) { int j = t >> 3, c = t & 7; s_cw[t] = cw_g[(c0 + c) * 27 + j]; }
    { int o = t >> 3, c = t & 7; s_cst[t] = cb_g[c0 + c] * g_sb1[p * 32 + o] + b1[o]; }

    ull acc2[8][2];
    #pragma unroll
    for (int cc = 0; cc < 8; ++cc) { acc2[cc][0] = 0ull; acc2[cc][1] = 0ull; }

    // stage1 thread coords: 2 adjacent o per thread
    int n0 = t * 2;
    int s1_hh = n0 >> 5, s1_o = n0 & 31;

    // tile loader: g_S slab rows hbase-1..hbase+16 (+w2 slab) into buffer `buf`
    const float4* g4 = (const float4*)g_S;
    auto load_tile = [&](int hb, int buf) {
        int hbase = hb * 16;
        #pragma unroll
        for (int pass = 0; pass < 6; ++pass) {
            int idx = t + 256 * pass;
            if (idx < 1296) {
                int r = idx / 24, cq = idx - r * 24;
                int i = r / 18, hr = r - i * 18;
                int hp = hbase - 1 + hr;
                float4 v = make_float4(0.f, 0.f, 0.f, 0.f);
                if (hp >= 0 && hp < 512) v = g4[((p * 3 + i) * 512 + hp) * 24 + cq];
                *(float4*)&s_S[buf][r * 96 + cq * 4] = v;
            }
        }
        for (int idx = t; idx < 512; idx += 256)
            s_w2[buf][idx] = w2[(hbase + (idx >> 5)) * 32 + (idx & 31)];
    };

    load_tile(0, 0);
    __syncthreads();

    for (int hb = 0; hb < 32; ++hb) {
        int cur = hb & 1, nxt = cur ^ 1;

        // prefetch next tile into the other buffer (overlaps with stage1)
        if (hb < 31) load_tile(hb + 1, nxt);

        // ---- stage 1: K=27 rank update, 8c(4 pairs) x 2n per thread ----
        {
            const float* bptr = &s_S[cur][s1_hh * 96 + s1_o];
            ull a1[4][2];
            #pragma unroll
            for (int cp = 0; cp < 4; ++cp) {
                a1[cp][0] = *(const ull*)&s_cst[s1_o * 8 + 2 * cp];
                a1[cp][1] = *(const ull*)&s_cst[(s1_o + 1) * 8 + 2 * cp];
            }
            #pragma unroll
            for (int i = 0; i < 3; ++i)
                #pragma unroll
                for (int ky = 0; ky < 3; ++ky)
                    #pragma unroll
                    for (int kx = 0; kx < 3; ++kx) {
                        const int off = (i * 18 + ky) * 96 + kx * 32;
                        const int j = (i * 3 + ky) * 3 + kx;
                        float2 bv = *(const float2*)&bptr[off];   // one LDS.64
                        ull bb0 = bro(bv.x);
                        ull bb1 = bro(bv.y);
                        #pragma unroll
                        for (int cp = 0; cp < 4; ++cp) {
                            ull a = *(const ull*)&s_cw[j * 8 + 2 * cp];
                            fma2(a1[cp][0], a, bb0);
                            fma2(a1[cp][1], a, bb1);
                        }
                    }
            #pragma unroll
            for (int cp = 0; cp < 4; ++cp)
                #pragma unroll
                for (int nn = 0; nn < 2; ++nn) {
                    float2 y = up2(a1[cp][nn]);
                    y.x = 1.f / (1.f + __expf(-y.x));
                    y.y = 1.f / (1.f + __expf(-y.y));
                    s_y1[((2 * cp) * 16 + s1_hh) * 32 + s1_o + nn] = y.x;
                    s_y1[((2 * cp + 1) * 16 + s1_hh) * 32 + s1_o + nn] = y.y;
                }
        }
        __syncthreads();

        // ---- stage 2: rank-16 update, packed over o2 pairs ----
        #pragma unroll 4
        for (int hh = 0; hh < 16; ++hh) {
            ull w2a = *(const ull*)&s_w2[cur][hh * 32 + wrp * 4];
            ull w2b = *(const ull*)&s_w2[cur][hh * 32 + wrp * 4 + 2];
            #pragma unroll
            for (int cc = 0; cc < 8; ++cc) {
                ull yv = bro(s_y1[(cc * 16 + hh) * 32 + lane]);
                fma2(acc2[cc][0], yv, w2a);
                fma2(acc2[cc][1], yv, w2b);
            }
        }
        __syncthreads();
    }

    // final epilogue: sigmoid + head split
    int n = lane;
    #pragma unroll
    for (int cc = 0; cc < 8; ++cc)
        #pragma unroll
        for (int jp = 0; jp < 2; ++jp) {
            float2 v = up2(acc2[cc][jp]);
            #pragma unroll
            for (int half = 0; half < 2; ++half) {
                int a = wrp * 4 + jp * 2 + half;
                float vv = (half == 0) ? v.x : v.y;
                float val = 1.f / (1.f + __expf(-(vv + b2[a])));
                int H = (a & 1) * 2 + (n & 1);
                int nsp = ((a >> 1) << 4) + (n >> 1);
                g_QKV[((p * 4 + H) * 768 + (c0 + cc)) * 256 + nsp] = val;
            }
        }
}

// ---------------- scores = Q K^T * temperature (f32x2) ----------------
__global__ __launch_bounds__(256) void k_gemm_qk(const float* temp) {
    int head = blockIdx.z, m0 = blockIdx.x * 128, n0 = blockIdx.y * 128;
    const float* A = g_QKV + (size_t)(0 + head) * 768 * 256;
    const float* B = g_QKV + (size_t)(4 + head) * 768 * 256;
    __shared__ float As[16][132];
    __shared__ float Bs[16][132];
    int t = threadIdx.x, tx = t & 15, ty = t >> 4;
    ull acc2[8][4];
    #pragma unroll
    for (int i = 0; i < 8; ++i)
        #pragma unroll
        for (int j = 0; j < 4; ++j) acc2[i][j] = 0ull;
    for (int kt = 0; kt < 16; ++kt) {
        int k0 = kt * 16;
        #pragma unroll
        for (int r = 0; r < 2; ++r) {
            int f4 = t + 256 * r, row = f4 >> 2, c4 = f4 & 3;
            float4 va = *(const float4*)&A[(size_t)(m0 + row) * 256 + k0 + c4 * 4];
            As[c4 * 4 + 0][row] = va.x; As[c4 * 4 + 1][row] = va.y;
            As[c4 * 4 + 2][row] = va.z; As[c4 * 4 + 3][row] = va.w;
            float4 vb = *(const float4*)&B[(size_t)(n0 + row) * 256 + k0 + c4 * 4];
            Bs[c4 * 4 + 0][row] = vb.x; Bs[c4 * 4 + 1][row] = vb.y;
            Bs[c4 * 4 + 2][row] = vb.z; Bs[c4 * 4 + 3][row] = vb.w;
        }
        __syncthreads();
        #pragma unroll
        for (int kk = 0; kk < 16; ++kk) {
            ull bp[4];
            #pragma unroll
            for (int jp = 0; jp < 4; ++jp) bp[jp] = *(const ull*)&Bs[kk][tx * 8 + 2 * jp];
            #pragma unroll
            for (int i = 0; i < 8; ++i) {
                ull ab = bro(As[kk][ty * 8 + i]);
                #pragma unroll
                for (int jp = 0; jp < 4; ++jp) fma2(acc2[i][jp], ab, bp[jp]);
            }
        }
        __syncthreads();
    }
    float tv = temp[head];
    #pragma unroll
    for (int i = 0; i < 8; ++i) {
        float* dst = &g_scores[(size_t)head * 589824 + (size_t)(m0 + ty * 8 + i) * 768 + n0 + tx * 8];
        #pragma unroll
        for (int jp = 0; jp < 4; ++jp) {
            float2 v = up2(acc2[i][jp]);
            dst[2 * jp] = v.x * tv;
            dst[2 * jp + 1] = v.y * tv;
        }
    }
}

// ---------------- softmax rows of 768 ----------------
__global__ __launch_bounds__(256) void k_softmax() {
    float* ptr = g_scores + (size_t)blockIdx.x * 768;
    int t = threadIdx.x;
    float v[3], mx = -1e30f;
    #pragma unroll
    for (int s = 0; s < 3; ++s) { v[s] = ptr[t + 256 * s]; mx = fmaxf(mx, v[s]); }
    __shared__ float red[256];
    red[t] = mx; __syncthreads();
    for (int st = 128; st > 0; st >>= 1) {
        if (t < st) red[t] = fmaxf(red[t], red[t + st]);
        __syncthreads();
    }
    mx = red[0]; __syncthreads();
    float sum = 0.f;
    #pragma unroll
    for (int s = 0; s < 3; ++s) { v[s] = __expf(v[s] - mx); sum += v[s]; }
    red[t] = sum; __syncthreads();
    for (int st = 128; st > 0; st >>= 1) {
        if (t < st) red[t] += red[t + st];
        __syncthreads();
    }
    float inv = 1.f / red[0];
    #pragma unroll
    for (int s = 0; s < 3; ++s) ptr[t + 256 * s] = v[s] * inv;
}

// ---------------- att = attn @ V (f32x2) ----------------
__global__ __launch_bounds__(256) void k_gemm_av() {
    int head = blockIdx.z, m0 = blockIdx.x * 128, n0 = blockIdx.y * 64;
    const float* A = g_scores + (size_t)head * 589824;
    const float* B = g_QKV + (size_t)(8 + head) * 768 * 256;
    __shared__ float As[16][132];
    __shared__ float Bs[16][68];
    int t = threadIdx.x, tx = t & 15, ty = t >> 4;
    ull acc2[8][2];
    #pragma unroll
    for (int i = 0; i < 8; ++i) { acc2[i][0] = 0ull; acc2[i][1] = 0ull; }
    for (int kt = 0; kt < 48; ++kt) {
        int k0 = kt * 16;
        #pragma unroll
        for (int r = 0; r < 2; ++r) {
            int f4 = t + 256 * r, row = f4 >> 2, c4 = f4 & 3;
            float4 va = *(const float4*)&A[(size_t)(m0 + row) * 768 + k0 + c4 * 4];
            As[c4 * 4 + 0][row] = va.x; As[c4 * 4 + 1][row] = va.y;
            As[c4 * 4 + 2][row] = va.z; As[c4 * 4 + 3][row] = va.w;
        }
        {
            int row = t >> 4, c4 = t & 15;
            float4 vb = *(const float4*)&B[(size_t)(k0 + row) * 256 + n0 + c4 * 4];
            Bs[row][c4 * 4 + 0] = vb.x; Bs[row][c4 * 4 + 1] = vb.y;
            Bs[row][c4 * 4 + 2] = vb.z; Bs[row][c4 * 4 + 3] = vb.w;
        }
        __syncthreads();
        #pragma unroll
        for (int kk = 0; kk < 16; ++kk) {
            ull bp0 = *(const ull*)&Bs[kk][tx * 4];
            ull bp1 = *(const ull*)&Bs[kk][tx * 4 + 2];
            #pragma unroll
            for (int i = 0; i < 8; ++i) {
                ull ab = bro(As[kk][ty * 8 + i]);
                fma2(acc2[i][0], ab, bp0);
                fma2(acc2[i][1], ab, bp1);
            }
        }
        __syncthreads();
    }
    #pragma unroll
    for (int i = 0; i < 8; ++i) {
        float* dst = &g_att[((size_t)head * 768 + m0 + ty * 8 + i) * 256 + n0 + tx * 4];
        float2 v0 = up2(acc2[i][0]);
        float2 v1 = up2(acc2[i][1]);
        dst[0] = v0.x; dst[1] = v0.y; dst[2] = v1.x; dst[3] = v1.y;
    }
}

// ---------------- fused FeedForward + residual ----------------
__global__ __launch_bounds__(256) void k_ff(
    const float* x, const float* pi_w, const float* pi_b,
    const float* dw_w, const float* dw_b, const float* po_w, const float* po_b,
    float* out)
{
    __shared__ float att_s[3][10][34];
    __shared__ float y_s[12][10][34];
    __shared__ float wts[189];
    int t = threadIdx.x;
    int x0 = blockIdx.x * 32, y0 = blockIdx.y * 8;
    if (t < 36) wts[t] = pi_w[t];
    else if (t < 48) wts[t] = pi_b[t - 36];
    else if (t < 156) wts[t] = dw_w[t - 48];
    else if (t < 168) wts[t] = dw_b[t - 156];
    else if (t < 186) wts[t] = po_w[t - 168];
    else if (t < 189) wts[t] = po_b[t - 186];
    for (int idx = t; idx < 1020; idx += 256) {
        int i = idx / 340, rem = idx % 340, ly = rem / 34, lx = rem % 34;
        int gy = y0 + ly - 1, gx = x0 + lx - 1;
        att_s[i][ly][lx] = (gy >= 0 && gy < 512 && gx >= 0 && gx < 512)
                           ? g_att[(i * 512 + gy) * 512 + gx] : 0.f;
    }
    __syncthreads();
    for (int idx = t; idx < 12 * 340; idx += 256) {
        int ch = idx / 340, rem = idx % 340, ly = rem / 34, lx = rem % 34;
        int gy = y0 + ly - 1, gx = x0 + lx - 1;
        float v = 0.f;
        if (gy >= 0 && gy < 512 && gx >= 0 && gx < 512) {
            v = wts[36 + ch];
            #pragma unroll
            for (int i = 0; i < 3; ++i) v += wts[ch * 3 + i] * att_s[i][ly][lx];
        }
        y_s[ch][ly][lx] = v;
    }
    __syncthreads();
    int lx = t & 31, ly = t >> 5;
    int gx = x0 + lx, gy = y0 + ly;
    float d[12];
    #pragma unroll
    for (int ch = 0; ch < 12; ++ch) {
        float v = wts[156 + ch];
        #pragma unroll
        for (int ky = 0; ky < 3; ++ky)
            #pragma unroll
            for (int kx = 0; kx < 3; ++kx)
                v += wts[48 + ch * 9 + ky * 3 + kx] * y_s[ch][ly + ky][lx + kx];
        d[ch] = v;
    }
    float g[6];
    #pragma unroll
    for (int c6 = 0; c6 < 6; ++c6) {
        float a = d[c6];
        g[c6] = 0.5f * a * (1.f + erff(a * 0.70710678f)) * d[6 + c6];
    }
    #pragma unroll
    for (int i = 0; i < 3; ++i) {
        float v = wts[186 + i];
        #pragma unroll
        for (int c6 = 0; c6 < 6; ++c6) v += wts[168 + i * 6 + c6] * g[c6];
        out[(i * 512 + gy) * 512 + gx] = x[(i * 512 + gy) * 512 + gx] + v;
    }
}

extern "C" void kernel_launch(void* const* d_in, const int* in_sizes, int n_in,
                              void* d_out, int out_size) {
    const float* x    = (const float*)d_in[0];
    const float* c_w  = (const float*)d_in[1];
    const float* c_b  = (const float*)d_in[2];
    const float* q_w1 = (const float*)d_in[3];
    const float* q_b1 = (const float*)d_in[4];
    const float* q_w2 = (const float*)d_in[5];
    const float* q_b2 = (const float*)d_in[6];
    const float* k_w1 = (const float*)d_in[7];
    const float* k_b1 = (const float*)d_in[8];
    const float* k_w2 = (const float*)d_in[9];
    const float* k_b2 = (const float*)d_in[10];
    const float* v_w1 = (const float*)d_in[11];
    const float* v_b1 = (const float*)d_in[12];
    const float* v_w2 = (const float*)d_in[13];
    const float* v_b2 = (const float*)d_in[14];
    const float* temp = (const float*)d_in[15];
    const float* pi_w = (const float*)d_in[16];
    const float* pi_b = (const float*)d_in[17];
    const float* dw_w = (const float*)d_in[18];
    const float* dw_b = (const float*)d_in[19];
    const float* po_w = (const float*)d_in[20];
    const float* po_b = (const float*)d_in[21];
    float* out = (float*)d_out;

    k_prep_wall<<<576, 256>>>(q_w1, k_w1, v_w1);
    k_prep_sb1<<<3, 256>>>(q_w1, k_w1, v_w1);
    k_gemm_S<<<dim3(48, 3), 256>>>(x);
    k_mlp<<<dim3(96, 3), 256>>>(c_w, c_b, q_b1, q_w2, q_b2,
                                k_b1, k_w2, k_b2, v_b1, v_w2, v_b2);
    k_gemm_qk<<<dim3(6, 6, 4), 256>>>(temp);
    k_softmax<<<3072, 256>>>();
    k_gemm_av<<<dim3(6, 4, 4), 256>>>();
    k_ff<<<dim3(16, 64), 256>>>(x, pi_w, pi_b, dw_w, dw_b, po_w, po_b, out);
}